// round 1
// baseline (speedup 1.0000x reference)
#include <cuda_runtime.h>
#include <math.h>

#define Wdim 14
#define Bdim 64
#define Cdim 256
#define WB   896          // W*B
#define NEGS 64
#define EPSF 1e-11f
#define MAX_ROWS 10752    // 12*14*64 (k=1)

// Scratch (no cudaMalloc allowed) — ~33 MB total
__device__ float g_zt  [MAX_ROWS * Cdim];
__device__ float g_ctx [MAX_ROWS * Cdim];
__device__ float g_flat[MAX_ROWS * Cdim];
__device__ float g_partial[4096];

// ---------------------------------------------------------------------------
// Transpose z[b,c,h+hoff,w] (or c[b,c,h,w]) -> dst[((h*W+w)*B+b)*256 + c]
// One block per (b,h). which: 0 -> g_zt, 1 -> g_ctx
// ---------------------------------------------------------------------------
__global__ void transpose_kernel(const float* __restrict__ src, int Hp, int hoff, int which)
{
    __shared__ float s[Cdim * 15];           // [c][w], padded stride 15
    int b = blockIdx.x / Hp;
    int h = blockIdx.x % Hp;
    const float* sp = src + (size_t)b * (Cdim * Wdim * Wdim) + (h + hoff) * Wdim;
    int t = threadIdx.x;
    for (int idx = t; idx < Cdim * Wdim; idx += 256) {
        int c = idx / Wdim, w = idx % Wdim;
        s[c * 15 + w] = sp[c * (Wdim * Wdim) + w];
    }
    __syncthreads();
    float* dst = which ? g_ctx : g_zt;
    for (int idx = t; idx < Wdim * Cdim; idx += 256) {
        int w = idx >> 8, c = idx & 255;
        dst[(size_t)((h * Wdim + w) * Bdim + b) * Cdim + c] = s[c * 15 + w];
    }
}

// ---------------------------------------------------------------------------
// g_flat[r, o] = sum_c g_zt[r, c] * Wm[o, c]        (M x 256, K = 256)
// 64x64 tiles, 16x16 threads, 4x4 microtile, BK=16
// ---------------------------------------------------------------------------
__global__ void gemm_kernel(const float* __restrict__ Wm)
{
    __shared__ float As[16][65];
    __shared__ float Ws[16][65];
    int tx = threadIdx.x, ty = threadIdx.y;
    int t  = ty * 16 + tx;
    int lr = t >> 2;       // 0..63 tile row
    int lq = t & 3;        // quad in K
    int rowBase = blockIdx.x * 64;
    int colBase = blockIdx.y * 64;
    float acc[4][4];
    #pragma unroll
    for (int i = 0; i < 4; i++)
        #pragma unroll
        for (int j = 0; j < 4; j++) acc[i][j] = 0.f;

    for (int k0 = 0; k0 < Cdim; k0 += 16) {
        float4 av = *(const float4*)(g_zt + (size_t)(rowBase + lr) * Cdim + k0 + lq * 4);
        float4 wv = *(const float4*)(Wm   + (size_t)(colBase + lr) * Cdim + k0 + lq * 4);
        As[lq*4+0][lr] = av.x; As[lq*4+1][lr] = av.y; As[lq*4+2][lr] = av.z; As[lq*4+3][lr] = av.w;
        Ws[lq*4+0][lr] = wv.x; Ws[lq*4+1][lr] = wv.y; Ws[lq*4+2][lr] = wv.z; Ws[lq*4+3][lr] = wv.w;
        __syncthreads();
        #pragma unroll
        for (int kk = 0; kk < 16; kk++) {
            float a0 = As[kk][ty*4+0], a1 = As[kk][ty*4+1], a2 = As[kk][ty*4+2], a3 = As[kk][ty*4+3];
            float b0 = Ws[kk][tx*4+0], b1 = Ws[kk][tx*4+1], b2 = Ws[kk][tx*4+2], b3 = Ws[kk][tx*4+3];
            acc[0][0] += a0*b0; acc[0][1] += a0*b1; acc[0][2] += a0*b2; acc[0][3] += a0*b3;
            acc[1][0] += a1*b0; acc[1][1] += a1*b1; acc[1][2] += a1*b2; acc[1][3] += a1*b3;
            acc[2][0] += a2*b0; acc[2][1] += a2*b1; acc[2][2] += a2*b2; acc[2][3] += a2*b3;
            acc[3][0] += a3*b0; acc[3][1] += a3*b1; acc[3][2] += a3*b2; acc[3][3] += a3*b3;
        }
        __syncthreads();
    }
    #pragma unroll
    for (int i = 0; i < 4; i++) {
        float4 v = make_float4(acc[i][0], acc[i][1], acc[i][2], acc[i][3]);
        *(float4*)(g_flat + (size_t)(rowBase + ty*4 + i) * Cdim + colBase + tx*4) = v;
    }
}

// ---------------------------------------------------------------------------
// Warp per row: main dot + 64 gathered neg dots, softmax, -log(p0+EPS)
// ---------------------------------------------------------------------------
__global__ void dot_kernel(const int* __restrict__ nidx, float wscale, int pofs)
{
    int warp = threadIdx.x >> 5;
    int lane = threadIdx.x & 31;
    int r = blockIdx.x * 8 + warp;

    const float* cr = g_ctx + (size_t)r * Cdim + lane * 8;
    float4 c0 = *(const float4*)(cr);
    float4 c1 = *(const float4*)(cr + 4);

    auto dotrow = [&](const float* __restrict__ p) {
        float4 a = *(const float4*)(p);
        float4 b = *(const float4*)(p + 4);
        float s = c0.x*a.x + c0.y*a.y + c0.z*a.z + c0.w*a.w
                + c1.x*b.x + c1.y*b.y + c1.z*b.z + c1.w*b.w;
        #pragma unroll
        for (int off = 16; off; off >>= 1)
            s += __shfl_xor_sync(0xffffffffu, s, off);
        return s;            // full sum on all lanes
    };

    float m = dotrow(g_flat + (size_t)r * Cdim + lane * 8);

    int i0 = nidx[r * NEGS + lane];
    int i1 = nidx[r * NEGS + 32 + lane];

    float l0 = 0.f, l1 = 0.f;
    #pragma unroll
    for (int n = 0; n < 32; n++) {
        int j = __shfl_sync(0xffffffffu, i0, n);
        float s = dotrow(g_flat + (size_t)j * Cdim + lane * 8);
        if (lane == n) l0 = s;
    }
    #pragma unroll
    for (int n = 0; n < 32; n++) {
        int j = __shfl_sync(0xffffffffu, i1, n);
        float s = dotrow(g_flat + (size_t)j * Cdim + lane * 8);
        if (lane == n) l1 = s;
    }

    // softmax over [m, l0(32), l1(32)]
    float mx = fmaxf(m, fmaxf(l0, l1));
    #pragma unroll
    for (int off = 16; off; off >>= 1)
        mx = fmaxf(mx, __shfl_xor_sync(0xffffffffu, mx, off));
    float se = expf(l0 - mx) + expf(l1 - mx);
    #pragma unroll
    for (int off = 16; off; off >>= 1)
        se += __shfl_xor_sync(0xffffffffu, se, off);
    float em = expf(m - mx);
    se += em;
    float p0 = em / se;
    float loss = -logf(p0 + EPSF);

    __shared__ float sacc[8];
    if (lane == 0) sacc[warp] = loss * wscale;
    __syncthreads();
    if (threadIdx.x == 0) {
        float s = 0.f;
        #pragma unroll
        for (int i = 0; i < 8; i++) s += sacc[i];
        g_partial[pofs + blockIdx.x] = s;
    }
}

// Deterministic final reduction
__global__ void finalize_kernel(int n, float* __restrict__ out)
{
    __shared__ float s[256];
    float acc = 0.f;
    for (int i = threadIdx.x; i < n; i += 256) acc += g_partial[i];
    s[threadIdx.x] = acc;
    __syncthreads();
    for (int st = 128; st; st >>= 1) {
        if (threadIdx.x < st) s[threadIdx.x] += s[threadIdx.x + st];
        __syncthreads();
    }
    if (threadIdx.x == 0) out[0] = s[0];
}

// ---------------------------------------------------------------------------
extern "C" void kernel_launch(void* const* d_in, const int* in_sizes, int n_in,
                              void* d_out, int out_size)
{
    const float* z   = (const float*)d_in[0];
    const float* cin = (const float*)d_in[1];
    const float* Wk  = (const float*)d_in[2];
    const int* nidx[3] = {(const int*)d_in[3], (const int*)d_in[4], (const int*)d_in[5]};
    float* out = (float*)d_out;

    int pofs = 0;
    for (int k = 1; k <= 3; k++) {
        int Hp   = Wdim - (k + 1);      // 12, 11, 10
        int rows = Hp * WB;             // multiple of 64 and 8
        transpose_kernel<<<Bdim * Hp, 256>>>(z,   Hp, k + 1, 0);
        transpose_kernel<<<Bdim * Hp, 256>>>(cin, Hp, 0,     1);
        gemm_kernel<<<dim3(rows / 64, Cdim / 64), dim3(16, 16)>>>(Wk + (size_t)(k - 1) * Cdim * Cdim);
        dot_kernel<<<rows / 8, 256>>>(nidx[k - 1], 1.0f / (3.0f * rows), pofs);
        pofs += rows / 8;
    }
    finalize_kernel<<<1, 256>>>(pofs, out);
}

// round 2
// speedup vs baseline: 1.8572x; 1.8572x over previous
#include <cuda_runtime.h>
#include <cuda_fp16.h>
#include <math.h>

#define Wdim 14
#define Bdim 64
#define Cdim 256
#define WB   896          // W*B
#define NEGS 64
#define EPSF 1e-11f
#define MAX_ROWS 10752    // 12*14*64 (k=1)

// Scratch (no cudaMalloc allowed)
__device__ float  g_zt  [MAX_ROWS * Cdim];   // tf32-rounded A
__device__ float  g_ctx [MAX_ROWS * Cdim];   // fp32 ctx
__device__ __half g_flat[MAX_ROWS * Cdim];   // fp16 GEMM output (gather table)
__device__ float  g_partial[4096];

__device__ __forceinline__ float tf32_round(float x) {
    float r;
    asm("cvt.rna.tf32.f32 %0, %1;" : "=f"(r) : "f"(x));
    return r;
}

// ---------------------------------------------------------------------------
// Transpose z[b,c,h+hoff,w] (or c[b,c,h,w]) -> dst[((h*W+w)*B+b)*256 + c]
// which: 0 -> g_zt (tf32-rounded), 1 -> g_ctx
// ---------------------------------------------------------------------------
__global__ void transpose_kernel(const float* __restrict__ src, int Hp, int hoff, int which)
{
    __shared__ float s[Cdim * 15];
    int b = blockIdx.x / Hp;
    int h = blockIdx.x % Hp;
    const float* sp = src + (size_t)b * (Cdim * Wdim * Wdim) + (h + hoff) * Wdim;
    int t = threadIdx.x;
    for (int idx = t; idx < Cdim * Wdim; idx += 256) {
        int c = idx / Wdim, w = idx % Wdim;
        s[c * 15 + w] = sp[c * (Wdim * Wdim) + w];
    }
    __syncthreads();
    if (which) {
        for (int idx = t; idx < Wdim * Cdim; idx += 256) {
            int w = idx >> 8, c = idx & 255;
            g_ctx[(size_t)((h * Wdim + w) * Bdim + b) * Cdim + c] = s[c * 15 + w];
        }
    } else {
        for (int idx = t; idx < Wdim * Cdim; idx += 256) {
            int w = idx >> 8, c = idx & 255;
            g_zt[(size_t)((h * Wdim + w) * Bdim + b) * Cdim + c] = tf32_round(s[c * 15 + w]);
        }
    }
}

// ---------------------------------------------------------------------------
// tf32 tensor-core GEMM: g_flat[r, o] = sum_c g_zt[r, c] * Wm[o, c]
// BM=128, BN=64, BK=32; 8 warps, warp tile 32x32 (m16n8k8 frags)
// ---------------------------------------------------------------------------
__device__ __forceinline__ void mma_tf32(float c[4], const unsigned a[4], const unsigned b[2])
{
    asm volatile(
        "mma.sync.aligned.m16n8k8.row.col.f32.tf32.tf32.f32 "
        "{%0,%1,%2,%3}, {%4,%5,%6,%7}, {%8,%9}, {%0,%1,%2,%3};\n"
        : "+f"(c[0]), "+f"(c[1]), "+f"(c[2]), "+f"(c[3])
        : "r"(a[0]), "r"(a[1]), "r"(a[2]), "r"(a[3]), "r"(b[0]), "r"(b[1]));
}

__global__ void gemm_tf32_kernel(const float* __restrict__ Wm)
{
    __shared__ float As[128 * 32];   // A[r][c] at r*32 + (c ^ (4*(r&7)))
    __shared__ float Bs[32 * 64];    // B[k][n] at k*64 + (n ^ (8*(k&3)))

    int t = threadIdx.x;
    int lane = t & 31;
    int w = t >> 5;
    int warp_m = w & 3;          // 4 m-warps
    int warp_n = w >> 2;         // 2 n-warps
    int rowBase = blockIdx.x * 128;
    int colBase = blockIdx.y * 64;

    float acc[2][4][4];
    #pragma unroll
    for (int i = 0; i < 2; i++)
        #pragma unroll
        for (int j = 0; j < 4; j++)
            #pragma unroll
            for (int e = 0; e < 4; e++) acc[i][j][e] = 0.f;

    for (int k0 = 0; k0 < Cdim; k0 += 32) {
        // ---- load A tile 128x32 (4 float4 per thread) ----
        #pragma unroll
        for (int p = 0; p < 4; p++) {
            int idx = p * 256 + t;
            int r = idx >> 3, cq = idx & 7;
            float4 v = *(const float4*)(g_zt + (size_t)(rowBase + r) * Cdim + k0 + cq * 4);
            v.x = tf32_round(v.x); v.y = tf32_round(v.y);
            v.z = tf32_round(v.z); v.w = tf32_round(v.w);
            *(float4*)(As + r * 32 + ((cq ^ (r & 7)) << 2)) = v;
        }
        // ---- load B tile 32x64 (Wm[n][k], 2 float4 per thread, transposed store) ----
        #pragma unroll
        for (int q = 0; q < 2; q++) {
            int idx = q * 256 + t;
            int n = idx & 63, kq = idx >> 6;       // kq 0..7
            float4 v = *(const float4*)(Wm + (size_t)(colBase + n) * Cdim + k0 + kq * 4);
            int kb = kq * 4;
            Bs[(kb + 0) * 64 + (n ^ 0)]  = tf32_round(v.x);
            Bs[(kb + 1) * 64 + (n ^ 8)]  = tf32_round(v.y);
            Bs[(kb + 2) * 64 + (n ^ 16)] = tf32_round(v.z);
            Bs[(kb + 3) * 64 + (n ^ 24)] = tf32_round(v.w);
        }
        __syncthreads();

        #pragma unroll
        for (int kt = 0; kt < 4; kt++) {
            unsigned a[2][4];
            int cA = kt * 8 + (lane & 3);
            #pragma unroll
            for (int i = 0; i < 2; i++) {
                int r0 = warp_m * 32 + i * 16 + (lane >> 2);
                int r1 = r0 + 8;
                a[i][0] = __float_as_uint(As[r0 * 32 + ( cA      ^ (4 * (r0 & 7)))]);
                a[i][1] = __float_as_uint(As[r1 * 32 + ( cA      ^ (4 * (r1 & 7)))]);
                a[i][2] = __float_as_uint(As[r0 * 32 + ((cA + 4) ^ (4 * (r0 & 7)))]);
                a[i][3] = __float_as_uint(As[r1 * 32 + ((cA + 4) ^ (4 * (r1 & 7)))]);
            }
            unsigned b[4][2];
            int kB = kt * 8 + (lane & 3);
            int sw = 8 * (kB & 3);
            #pragma unroll
            for (int j = 0; j < 4; j++) {
                int n = warp_n * 32 + j * 8 + (lane >> 2);
                b[j][0] = __float_as_uint(Bs[ kB      * 64 + (n ^ sw)]);
                b[j][1] = __float_as_uint(Bs[(kB + 4) * 64 + (n ^ sw)]);
            }
            #pragma unroll
            for (int i = 0; i < 2; i++)
                #pragma unroll
                for (int j = 0; j < 4; j++)
                    mma_tf32(acc[i][j], a[i], b[j]);
        }
        __syncthreads();
    }

    // epilogue: write half2
    #pragma unroll
    for (int i = 0; i < 2; i++) {
        #pragma unroll
        for (int j = 0; j < 4; j++) {
            int row = rowBase + warp_m * 32 + i * 16 + (lane >> 2);
            int col = colBase + warp_n * 32 + j * 8 + 2 * (lane & 3);
            *(__half2*)(g_flat + (size_t)row * Cdim + col) =
                __floats2half2_rn(acc[i][j][0], acc[i][j][1]);
            *(__half2*)(g_flat + (size_t)(row + 8) * Cdim + col) =
                __floats2half2_rn(acc[i][j][2], acc[i][j][3]);
        }
    }
}

// ---------------------------------------------------------------------------
// Warp per row: main dot + 64 gathered neg dots (fp16 table), softmax, loss
// ---------------------------------------------------------------------------
__global__ void dot_kernel(const int* __restrict__ nidx, float wscale, int pofs)
{
    int warp = threadIdx.x >> 5;
    int lane = threadIdx.x & 31;
    int r = blockIdx.x * 8 + warp;

    const float* cr = g_ctx + (size_t)r * Cdim + lane * 8;
    float4 c0 = *(const float4*)(cr);
    float4 c1 = *(const float4*)(cr + 4);

    auto dotrow = [&](int j) {
        uint4 v = *(const uint4*)(g_flat + (size_t)j * Cdim + lane * 8);
        float2 f0 = __half22float2(*(__half2*)&v.x);
        float2 f1 = __half22float2(*(__half2*)&v.y);
        float2 f2 = __half22float2(*(__half2*)&v.z);
        float2 f3 = __half22float2(*(__half2*)&v.w);
        float s = f0.x*c0.x + f0.y*c0.y + f1.x*c0.z + f1.y*c0.w
                + f2.x*c1.x + f2.y*c1.y + f3.x*c1.z + f3.y*c1.w;
        #pragma unroll
        for (int off = 16; off; off >>= 1)
            s += __shfl_xor_sync(0xffffffffu, s, off);
        return s;
    };

    float m = dotrow(r);

    int i0 = nidx[r * NEGS + lane];
    int i1 = nidx[r * NEGS + 32 + lane];

    float l0 = 0.f, l1 = 0.f;
    #pragma unroll
    for (int n = 0; n < 32; n++) {
        int j = __shfl_sync(0xffffffffu, i0, n);
        float s = dotrow(j);
        if (lane == n) l0 = s;
    }
    #pragma unroll
    for (int n = 0; n < 32; n++) {
        int j = __shfl_sync(0xffffffffu, i1, n);
        float s = dotrow(j);
        if (lane == n) l1 = s;
    }

    float mx = fmaxf(m, fmaxf(l0, l1));
    #pragma unroll
    for (int off = 16; off; off >>= 1)
        mx = fmaxf(mx, __shfl_xor_sync(0xffffffffu, mx, off));
    float se = expf(l0 - mx) + expf(l1 - mx);
    #pragma unroll
    for (int off = 16; off; off >>= 1)
        se += __shfl_xor_sync(0xffffffffu, se, off);
    float em = expf(m - mx);
    se += em;
    float p0 = em / se;
    float loss = -logf(p0 + EPSF);

    __shared__ float sacc[8];
    if (lane == 0) sacc[warp] = loss * wscale;
    __syncthreads();
    if (threadIdx.x == 0) {
        float s = 0.f;
        #pragma unroll
        for (int i = 0; i < 8; i++) s += sacc[i];
        g_partial[pofs + blockIdx.x] = s;
    }
}

// Deterministic final reduction
__global__ void finalize_kernel(int n, float* __restrict__ out)
{
    __shared__ float s[256];
    float acc = 0.f;
    for (int i = threadIdx.x; i < n; i += 256) acc += g_partial[i];
    s[threadIdx.x] = acc;
    __syncthreads();
    for (int st = 128; st; st >>= 1) {
        if (threadIdx.x < st) s[threadIdx.x] += s[threadIdx.x + st];
        __syncthreads();
    }
    if (threadIdx.x == 0) out[0] = s[0];
}

// ---------------------------------------------------------------------------
extern "C" void kernel_launch(void* const* d_in, const int* in_sizes, int n_in,
                              void* d_out, int out_size)
{
    const float* z   = (const float*)d_in[0];
    const float* cin = (const float*)d_in[1];
    const float* Wk  = (const float*)d_in[2];
    const int* nidx[3] = {(const int*)d_in[3], (const int*)d_in[4], (const int*)d_in[5]};
    float* out = (float*)d_out;

    int pofs = 0;
    for (int k = 1; k <= 3; k++) {
        int Hp   = Wdim - (k + 1);      // 12, 11, 10
        int rows = Hp * WB;             // multiple of 128 and 8
        transpose_kernel<<<Bdim * Hp, 256>>>(z,   Hp, k + 1, 0);
        transpose_kernel<<<Bdim * Hp, 256>>>(cin, Hp, 0,     1);
        gemm_tf32_kernel<<<dim3(rows / 128, Cdim / 64), 256>>>(Wk + (size_t)(k - 1) * Cdim * Cdim);
        dot_kernel<<<rows / 8, 256>>>(nidx[k - 1], 1.0f / (3.0f * rows), pofs);
        pofs += rows / 8;
    }
    finalize_kernel<<<1, 256>>>(pofs, out);
}

// round 4
// speedup vs baseline: 2.8986x; 1.5607x over previous
#include <cuda_runtime.h>
#include <cuda_fp16.h>
#include <math.h>

#define Wdim 14
#define Bdim 64
#define Cdim 256
#define WB   896          // W*B
#define NEGS 64
#define EPSF 1e-11f
#define FULL_ROWS 12544   // 14*14*64
#define MAX_ROWS  10752   // 12*14*64 (k=1)

// Scratch (no cudaMalloc allowed)
__device__ float  g_zt  [FULL_ROWS * Cdim];  // tf32-rounded, full h range
__device__ float  g_ctx [FULL_ROWS * Cdim];  // fp32 ctx, full h range
__device__ __half g_flat[MAX_ROWS * Cdim];   // fp16 GEMM output (gather table)
__device__ float  g_partial[4096];

__device__ __forceinline__ float tf32_round(float x) {
    float r;
    asm("cvt.rna.tf32.f32 %0, %1;" : "=f"(r) : "f"(x));
    return r;
}

// ---------------------------------------------------------------------------
// Full transpose: src[b,c,h,w] -> dst[((h*W+w)*B+b)*256 + c], h = 0..13
// which: 0 -> g_zt (tf32-rounded), 1 -> g_ctx
// ---------------------------------------------------------------------------
__global__ void transpose_kernel(const float* __restrict__ src, int which)
{
    __shared__ float s[Cdim * 15];
    int b = blockIdx.x / Wdim;
    int h = blockIdx.x % Wdim;
    const float* sp = src + (size_t)b * (Cdim * Wdim * Wdim) + h * Wdim;
    int t = threadIdx.x;
    for (int idx = t; idx < Cdim * Wdim; idx += 256) {
        int c = idx / Wdim, w = idx % Wdim;
        s[c * 15 + w] = sp[c * (Wdim * Wdim) + w];
    }
    __syncthreads();
    if (which) {
        for (int idx = t; idx < Wdim * Cdim; idx += 256) {
            int w = idx >> 8, c = idx & 255;
            g_ctx[(size_t)((h * Wdim + w) * Bdim + b) * Cdim + c] = s[c * 15 + w];
        }
    } else {
        for (int idx = t; idx < Wdim * Cdim; idx += 256) {
            int w = idx >> 8, c = idx & 255;
            g_zt[(size_t)((h * Wdim + w) * Bdim + b) * Cdim + c] = tf32_round(s[c * 15 + w]);
        }
    }
}

// ---------------------------------------------------------------------------
// tf32 tensor-core GEMM: g_flat[r, o] = sum_c g_zt[rowOfs + r, c] * Wm[o, c]
// BM=128, BN=64, BK=32; 8 warps, warp tile 32x32 (m16n8k8 frags)
// NOTE: rowOfs passed as int — device-symbol arithmetic must happen on device.
// ---------------------------------------------------------------------------
__device__ __forceinline__ void mma_tf32(float c[4], const unsigned a[4], const unsigned b[2])
{
    asm volatile(
        "mma.sync.aligned.m16n8k8.row.col.f32.tf32.tf32.f32 "
        "{%0,%1,%2,%3}, {%4,%5,%6,%7}, {%8,%9}, {%0,%1,%2,%3};\n"
        : "+f"(c[0]), "+f"(c[1]), "+f"(c[2]), "+f"(c[3])
        : "r"(a[0]), "r"(a[1]), "r"(a[2]), "r"(a[3]), "r"(b[0]), "r"(b[1]));
}

__global__ void gemm_tf32_kernel(int rowOfs, const float* __restrict__ Wm)
{
    __shared__ float As[128 * 32];   // A[r][c] at r*32 + (c ^ (4*(r&7)))
    __shared__ float Bs[32 * 64];    // B[k][n] at k*64 + (n ^ (8*(k&3)))

    const float* A = g_zt + (size_t)rowOfs * Cdim;

    int t = threadIdx.x;
    int lane = t & 31;
    int w = t >> 5;
    int warp_m = w & 3;
    int warp_n = w >> 2;
    int rowBase = blockIdx.x * 128;
    int colBase = blockIdx.y * 64;

    float acc[2][4][4];
    #pragma unroll
    for (int i = 0; i < 2; i++)
        #pragma unroll
        for (int j = 0; j < 4; j++)
            #pragma unroll
            for (int e = 0; e < 4; e++) acc[i][j][e] = 0.f;

    for (int k0 = 0; k0 < Cdim; k0 += 32) {
        #pragma unroll
        for (int p = 0; p < 4; p++) {
            int idx = p * 256 + t;
            int r = idx >> 3, cq = idx & 7;
            float4 v = *(const float4*)(A + (size_t)(rowBase + r) * Cdim + k0 + cq * 4);
            *(float4*)(As + r * 32 + ((cq ^ (r & 7)) << 2)) = v;
        }
        #pragma unroll
        for (int q = 0; q < 2; q++) {
            int idx = q * 256 + t;
            int n = idx & 63, kq = idx >> 6;
            float4 v = *(const float4*)(Wm + (size_t)(colBase + n) * Cdim + k0 + kq * 4);
            int kb = kq * 4;
            Bs[(kb + 0) * 64 + (n ^ 0)]  = tf32_round(v.x);
            Bs[(kb + 1) * 64 + (n ^ 8)]  = tf32_round(v.y);
            Bs[(kb + 2) * 64 + (n ^ 16)] = tf32_round(v.z);
            Bs[(kb + 3) * 64 + (n ^ 24)] = tf32_round(v.w);
        }
        __syncthreads();

        #pragma unroll
        for (int kt = 0; kt < 4; kt++) {
            unsigned a[2][4];
            int cA = kt * 8 + (lane & 3);
            #pragma unroll
            for (int i = 0; i < 2; i++) {
                int r0 = warp_m * 32 + i * 16 + (lane >> 2);
                int r1 = r0 + 8;
                a[i][0] = __float_as_uint(As[r0 * 32 + ( cA      ^ (4 * (r0 & 7)))]);
                a[i][1] = __float_as_uint(As[r1 * 32 + ( cA      ^ (4 * (r1 & 7)))]);
                a[i][2] = __float_as_uint(As[r0 * 32 + ((cA + 4) ^ (4 * (r0 & 7)))]);
                a[i][3] = __float_as_uint(As[r1 * 32 + ((cA + 4) ^ (4 * (r1 & 7)))]);
            }
            unsigned b[4][2];
            int kB = kt * 8 + (lane & 3);
            int sw = 8 * (kB & 3);
            #pragma unroll
            for (int j = 0; j < 4; j++) {
                int n = warp_n * 32 + j * 8 + (lane >> 2);
                b[j][0] = __float_as_uint(Bs[ kB      * 64 + (n ^ sw)]);
                b[j][1] = __float_as_uint(Bs[(kB + 4) * 64 + (n ^ sw)]);
            }
            #pragma unroll
            for (int i = 0; i < 2; i++)
                #pragma unroll
                for (int j = 0; j < 4; j++)
                    mma_tf32(acc[i][j], a[i], b[j]);
        }
        __syncthreads();
    }

    #pragma unroll
    for (int i = 0; i < 2; i++) {
        #pragma unroll
        for (int j = 0; j < 4; j++) {
            int row = rowBase + warp_m * 32 + i * 16 + (lane >> 2);
            int col = colBase + warp_n * 32 + j * 8 + 2 * (lane & 3);
            *(__half2*)(g_flat + (size_t)row * Cdim + col) =
                __floats2half2_rn(acc[i][j][0], acc[i][j][1]);
            *(__half2*)(g_flat + (size_t)(row + 8) * Cdim + col) =
                __floats2half2_rn(acc[i][j][2], acc[i][j][3]);
        }
    }
}

// ---------------------------------------------------------------------------
// Warp per row: main dot + 64 gathered neg dots (fp16 table, HFMA2 math),
// butterfly multi-reduction (31 shfl per 32 negs), softmax, loss.
// ---------------------------------------------------------------------------
__global__ void __launch_bounds__(256) dot_kernel(const int* __restrict__ nidx,
                                                  float wscale, int pofs)
{
    int warp = threadIdx.x >> 5;
    int lane = threadIdx.x & 31;
    int r = blockIdx.x * 8 + warp;

    // ctx slice as 4x half2
    const float* cr = g_ctx + (size_t)r * Cdim + lane * 8;
    float4 cf0 = *(const float4*)(cr);
    float4 cf1 = *(const float4*)(cr + 4);
    __half2 c0 = __floats2half2_rn(cf0.x, cf0.y);
    __half2 c1 = __floats2half2_rn(cf0.z, cf0.w);
    __half2 c2 = __floats2half2_rn(cf1.x, cf1.y);
    __half2 c3 = __floats2half2_rn(cf1.z, cf1.w);

    auto partial = [&](int j) -> float {
        uint4 v = *(const uint4*)(g_flat + (size_t)j * Cdim + lane * 8);
        __half2 acc = __hmul2(*(__half2*)&v.x, c0);
        acc = __hfma2(*(__half2*)&v.y, c1, acc);
        acc = __hfma2(*(__half2*)&v.z, c2, acc);
        acc = __hfma2(*(__half2*)&v.w, c3, acc);
        float2 f = __half22float2(acc);
        return f.x + f.y;
    };

    // main logit (full warp reduce)
    float m = partial(r);
    #pragma unroll
    for (int off = 16; off; off >>= 1)
        m += __shfl_xor_sync(0xffffffffu, m, off);

    int i0 = nidx[r * NEGS + lane];
    int i1 = nidx[r * NEGS + 32 + lane];

    float P[32];

    // ---- group A: negs 0..31 ----
    #pragma unroll
    for (int n = 0; n < 32; n++)
        P[n] = partial(__shfl_sync(0xffffffffu, i0, n));
    #pragma unroll
    for (int b = 16; b; b >>= 1) {
        #pragma unroll
        for (int j = 0; j < b; j++) {
            bool up = (lane & b) != 0;
            float keep = up ? P[j + b] : P[j];
            float send = up ? P[j] : P[j + b];
            P[j] = keep + __shfl_xor_sync(0xffffffffu, send, b);
        }
    }
    float l0 = P[0];     // lane l holds logit of neg l

    // ---- group B: negs 32..63 ----
    #pragma unroll
    for (int n = 0; n < 32; n++)
        P[n] = partial(__shfl_sync(0xffffffffu, i1, n));
    #pragma unroll
    for (int b = 16; b; b >>= 1) {
        #pragma unroll
        for (int j = 0; j < b; j++) {
            bool up = (lane & b) != 0;
            float keep = up ? P[j + b] : P[j];
            float send = up ? P[j] : P[j + b];
            P[j] = keep + __shfl_xor_sync(0xffffffffu, send, b);
        }
    }
    float l1 = P[0];

    // softmax over [m, l0(32), l1(32)]
    float mx = fmaxf(m, fmaxf(l0, l1));
    #pragma unroll
    for (int off = 16; off; off >>= 1)
        mx = fmaxf(mx, __shfl_xor_sync(0xffffffffu, mx, off));
    float se = expf(l0 - mx) + expf(l1 - mx);
    #pragma unroll
    for (int off = 16; off; off >>= 1)
        se += __shfl_xor_sync(0xffffffffu, se, off);
    float em = expf(m - mx);
    se += em;
    float p0 = em / se;
    float loss = -logf(p0 + EPSF);

    __shared__ float sacc[8];
    if (lane == 0) sacc[warp] = loss * wscale;
    __syncthreads();
    if (threadIdx.x == 0) {
        float s = 0.f;
        #pragma unroll
        for (int i = 0; i < 8; i++) s += sacc[i];
        g_partial[pofs + blockIdx.x] = s;
    }
}

// Deterministic final reduction
__global__ void finalize_kernel(int n, float* __restrict__ out)
{
    __shared__ float s[256];
    float acc = 0.f;
    for (int i = threadIdx.x; i < n; i += 256) acc += g_partial[i];
    s[threadIdx.x] = acc;
    __syncthreads();
    for (int st = 128; st; st >>= 1) {
        if (threadIdx.x < st) s[threadIdx.x] += s[threadIdx.x + st];
        __syncthreads();
    }
    if (threadIdx.x == 0) out[0] = s[0];
}

// ---------------------------------------------------------------------------
extern "C" void kernel_launch(void* const* d_in, const int* in_sizes, int n_in,
                              void* d_out, int out_size)
{
    const float* z   = (const float*)d_in[0];
    const float* cin = (const float*)d_in[1];
    const float* Wk  = (const float*)d_in[2];
    const int* nidx[3] = {(const int*)d_in[3], (const int*)d_in[4], (const int*)d_in[5]};
    float* out = (float*)d_out;

    transpose_kernel<<<Bdim * Wdim, 256>>>(z,   0);
    transpose_kernel<<<Bdim * Wdim, 256>>>(cin, 1);

    int pofs = 0;
    for (int k = 1; k <= 3; k++) {
        int Hp   = Wdim - (k + 1);      // 12, 11, 10
        int rows = Hp * WB;             // multiple of 128 and 8
        gemm_tf32_kernel<<<dim3(rows / 128, Cdim / 64), 256>>>(
            (k + 1) * WB,                              // row offset into g_zt (device-side)
            Wk + (size_t)(k - 1) * Cdim * Cdim);
        dot_kernel<<<rows / 8, 256>>>(nidx[k - 1], 1.0f / (3.0f * rows), pofs);
        pofs += rows / 8;
    }
    finalize_kernel<<<1, 256>>>(pofs, out);
}

// round 5
// speedup vs baseline: 3.2967x; 1.1373x over previous
#include <cuda_runtime.h>
#include <cuda_fp16.h>
#include <math.h>

#define Wdim 14
#define Bdim 64
#define Cdim 256
#define WB   896          // W*B
#define NEGS 64
#define EPSF 1e-11f
#define FULL_ROWS 12544   // 14*14*64
#define TOT_ROWS  29568   // 10752+9856+8960

// per-k constants (kk = 0,1,2)
#define ROWS0 10752
#define ROWS1 9856
#define ROWS2 8960
#define MB0 84            // rows/128
#define MB1 77
#define MB2 70
#define DB0 1344          // rows/8
#define DB1 1232
#define DB2 1120

// Scratch (no cudaMalloc allowed)
__device__ float  g_zt  [FULL_ROWS * Cdim];  // tf32-rounded z, full h range
__device__ __half g_ctxh[FULL_ROWS * Cdim];  // fp16 ctx, full h range
__device__ __half g_flat[TOT_ROWS * Cdim];   // fp16 GEMM output, all k concatenated
__device__ float  g_partial[4096];

__device__ __forceinline__ float tf32_round(float x) {
    float r;
    asm("cvt.rna.tf32.f32 %0, %1;" : "=f"(r) : "f"(x));
    return r;
}

// ---------------------------------------------------------------------------
// Fused transpose: blocks [0,896) -> z into g_zt (tf32), [896,1792) -> c into g_ctxh
// src[b,c,h,w] -> dst[((h*W+w)*B+b)*256 + c]
// ---------------------------------------------------------------------------
__global__ void transpose_kernel(const float* __restrict__ z, const float* __restrict__ cin)
{
    __shared__ float s[Cdim * 15];
    int which = blockIdx.x >= (Bdim * Wdim);
    int bh = blockIdx.x - which * (Bdim * Wdim);
    int b = bh / Wdim;
    int h = bh % Wdim;
    const float* sp = (which ? cin : z) + (size_t)b * (Cdim * Wdim * Wdim) + h * Wdim;
    int t = threadIdx.x;
    for (int idx = t; idx < Cdim * Wdim; idx += 256) {
        int c = idx / Wdim, w = idx % Wdim;
        s[c * 15 + w] = sp[c * (Wdim * Wdim) + w];
    }
    __syncthreads();
    if (which) {
        for (int idx = t; idx < Wdim * Cdim; idx += 256) {
            int w = idx >> 8, c = idx & 255;
            g_ctxh[(size_t)((h * Wdim + w) * Bdim + b) * Cdim + c] = __float2half_rn(s[c * 15 + w]);
        }
    } else {
        for (int idx = t; idx < Wdim * Cdim; idx += 256) {
            int w = idx >> 8, c = idx & 255;
            g_zt[(size_t)((h * Wdim + w) * Bdim + b) * Cdim + c] = tf32_round(s[c * 15 + w]);
        }
    }
}

// ---------------------------------------------------------------------------
// Fused tf32 GEMM, all 3 k's in one launch. grid = (231, 4)
// g_flat[fOfs + r, o] = sum_c g_zt[zOfs + r, c] * Wk[kk][o, c]
// BM=128, BN=64, BK=32, software-pipelined (register prefetch).
// ---------------------------------------------------------------------------
__device__ __forceinline__ void mma_tf32(float c[4], const unsigned a[4], const unsigned b[2])
{
    asm volatile(
        "mma.sync.aligned.m16n8k8.row.col.f32.tf32.tf32.f32 "
        "{%0,%1,%2,%3}, {%4,%5,%6,%7}, {%8,%9}, {%0,%1,%2,%3};\n"
        : "+f"(c[0]), "+f"(c[1]), "+f"(c[2]), "+f"(c[3])
        : "r"(a[0]), "r"(a[1]), "r"(a[2]), "r"(a[3]), "r"(b[0]), "r"(b[1]));
}

__global__ void __launch_bounds__(256) gemm_tf32_kernel(const float* __restrict__ Wk)
{
    __shared__ float As[128 * 32];   // A[r][c] at r*32 + (c ^ (4*(r&7)))
    __shared__ float Bs[32 * 64];    // B[k][n] at k*64 + (n ^ (8*(k&3)))

    int bx = blockIdx.x;
    int kk, mb;
    if (bx < MB0)            { kk = 0; mb = bx; }
    else if (bx < MB0 + MB1) { kk = 1; mb = bx - MB0; }
    else                     { kk = 2; mb = bx - MB0 - MB1; }

    const float* A  = g_zt + (size_t)(kk + 2) * WB * Cdim;
    const float* Wm = Wk + (size_t)kk * Cdim * Cdim;
    __half* F = g_flat + (size_t)(kk == 0 ? 0 : (kk == 1 ? ROWS0 : ROWS0 + ROWS1)) * Cdim;

    int t = threadIdx.x;
    int lane = t & 31;
    int w = t >> 5;
    int warp_m = w & 3;
    int warp_n = w >> 2;
    int rowBase = mb * 128;
    int colBase = blockIdx.y * 64;

    float acc[2][4][4];
    #pragma unroll
    for (int i = 0; i < 2; i++)
        #pragma unroll
        for (int j = 0; j < 4; j++)
            #pragma unroll
            for (int e = 0; e < 4; e++) acc[i][j][e] = 0.f;

    float4 ra[4], rb[2];
    // prefetch tile k0=0
    #pragma unroll
    for (int p = 0; p < 4; p++) {
        int idx = p * 256 + t;
        int r = idx >> 3, cq = idx & 7;
        ra[p] = *(const float4*)(A + (size_t)(rowBase + r) * Cdim + cq * 4);
    }
    #pragma unroll
    for (int q = 0; q < 2; q++) {
        int idx = q * 256 + t;
        int n = idx & 63, kq = idx >> 6;
        rb[q] = *(const float4*)(Wm + (size_t)(colBase + n) * Cdim + kq * 4);
    }

    for (int k0 = 0; k0 < Cdim; k0 += 32) {
        // store current tile to smem
        #pragma unroll
        for (int p = 0; p < 4; p++) {
            int idx = p * 256 + t;
            int r = idx >> 3, cq = idx & 7;
            *(float4*)(As + r * 32 + ((cq ^ (r & 7)) << 2)) = ra[p];
        }
        #pragma unroll
        for (int q = 0; q < 2; q++) {
            int idx = q * 256 + t;
            int n = idx & 63, kq = idx >> 6;
            int kb = kq * 4;
            Bs[(kb + 0) * 64 + (n ^ 0)]  = tf32_round(rb[q].x);
            Bs[(kb + 1) * 64 + (n ^ 8)]  = tf32_round(rb[q].y);
            Bs[(kb + 2) * 64 + (n ^ 16)] = tf32_round(rb[q].z);
            Bs[(kb + 3) * 64 + (n ^ 24)] = tf32_round(rb[q].w);
        }
        __syncthreads();

        // prefetch next tile (overlaps with compute)
        if (k0 + 32 < Cdim) {
            #pragma unroll
            for (int p = 0; p < 4; p++) {
                int idx = p * 256 + t;
                int r = idx >> 3, cq = idx & 7;
                ra[p] = *(const float4*)(A + (size_t)(rowBase + r) * Cdim + k0 + 32 + cq * 4);
            }
            #pragma unroll
            for (int q = 0; q < 2; q++) {
                int idx = q * 256 + t;
                int n = idx & 63, kq = idx >> 6;
                rb[q] = *(const float4*)(Wm + (size_t)(colBase + n) * Cdim + k0 + 32 + kq * 4);
            }
        }

        #pragma unroll
        for (int kt = 0; kt < 4; kt++) {
            unsigned a[2][4];
            int cA = kt * 8 + (lane & 3);
            #pragma unroll
            for (int i = 0; i < 2; i++) {
                int r0 = warp_m * 32 + i * 16 + (lane >> 2);
                int r1 = r0 + 8;
                a[i][0] = __float_as_uint(As[r0 * 32 + ( cA      ^ (4 * (r0 & 7)))]);
                a[i][1] = __float_as_uint(As[r1 * 32 + ( cA      ^ (4 * (r1 & 7)))]);
                a[i][2] = __float_as_uint(As[r0 * 32 + ((cA + 4) ^ (4 * (r0 & 7)))]);
                a[i][3] = __float_as_uint(As[r1 * 32 + ((cA + 4) ^ (4 * (r1 & 7)))]);
            }
            unsigned b[4][2];
            int kB = kt * 8 + (lane & 3);
            int sw = 8 * (kB & 3);
            #pragma unroll
            for (int j = 0; j < 4; j++) {
                int n = warp_n * 32 + j * 8 + (lane >> 2);
                b[j][0] = __float_as_uint(Bs[ kB      * 64 + (n ^ sw)]);
                b[j][1] = __float_as_uint(Bs[(kB + 4) * 64 + (n ^ sw)]);
            }
            #pragma unroll
            for (int i = 0; i < 2; i++)
                #pragma unroll
                for (int j = 0; j < 4; j++)
                    mma_tf32(acc[i][j], a[i], b[j]);
        }
        __syncthreads();
    }

    #pragma unroll
    for (int i = 0; i < 2; i++) {
        #pragma unroll
        for (int j = 0; j < 4; j++) {
            int row = rowBase + warp_m * 32 + i * 16 + (lane >> 2);
            int col = colBase + warp_n * 32 + j * 8 + 2 * (lane & 3);
            *(__half2*)(F + (size_t)row * Cdim + col) =
                __floats2half2_rn(acc[i][j][0], acc[i][j][1]);
            *(__half2*)(F + (size_t)(row + 8) * Cdim + col) =
                __floats2half2_rn(acc[i][j][2], acc[i][j][3]);
        }
    }
}

// ---------------------------------------------------------------------------
// Fused dot kernel, all 3 k's in one launch. grid = 3696 blocks of 8 warps.
// Warp per row: main dot + 64 gathered neg dots, butterfly multi-reduce.
// ---------------------------------------------------------------------------
__global__ void __launch_bounds__(256) dot_kernel(const int* __restrict__ n1,
                                                  const int* __restrict__ n2,
                                                  const int* __restrict__ n3)
{
    int bx = blockIdx.x;
    int kk, lb;
    if (bx < DB0)            { kk = 0; lb = bx; }
    else if (bx < DB0 + DB1) { kk = 1; lb = bx - DB0; }
    else                     { kk = 2; lb = bx - DB0 - DB1; }
    const int* nidx = kk == 0 ? n1 : (kk == 1 ? n2 : n3);
    int rows    = kk == 0 ? ROWS0 : (kk == 1 ? ROWS1 : ROWS2);
    int flatOfs = kk == 0 ? 0     : (kk == 1 ? ROWS0 : ROWS0 + ROWS1);

    int warp = threadIdx.x >> 5;
    int lane = threadIdx.x & 31;
    int r = lb * 8 + warp;          // local row within this k

    // ctx slice (fp16, direct load)
    uint4 cv = *(const uint4*)(g_ctxh + (size_t)r * Cdim + lane * 8);
    __half2 c0 = *(__half2*)&cv.x;
    __half2 c1 = *(__half2*)&cv.y;
    __half2 c2 = *(__half2*)&cv.z;
    __half2 c3 = *(__half2*)&cv.w;

    const __half* fbase = g_flat + (size_t)flatOfs * Cdim + lane * 8;

    auto partial = [&](int j) -> float {
        uint4 v = *(const uint4*)(fbase + (size_t)j * Cdim);
        __half2 acc = __hmul2(*(__half2*)&v.x, c0);
        acc = __hfma2(*(__half2*)&v.y, c1, acc);
        acc = __hfma2(*(__half2*)&v.z, c2, acc);
        acc = __hfma2(*(__half2*)&v.w, c3, acc);
        float2 f = __half22float2(acc);
        return f.x + f.y;
    };

    // main logit (full warp reduce)
    float m = partial(r);
    #pragma unroll
    for (int off = 16; off; off >>= 1)
        m += __shfl_xor_sync(0xffffffffu, m, off);

    int i0 = nidx[r * NEGS + lane];
    int i1 = nidx[r * NEGS + 32 + lane];

    float P[32];

    // ---- group A: negs 0..31 ----
    #pragma unroll
    for (int n = 0; n < 32; n++)
        P[n] = partial(__shfl_sync(0xffffffffu, i0, n));
    #pragma unroll
    for (int b = 16; b; b >>= 1) {
        #pragma unroll
        for (int j = 0; j < b; j++) {
            bool up = (lane & b) != 0;
            float keep = up ? P[j + b] : P[j];
            float send = up ? P[j] : P[j + b];
            P[j] = keep + __shfl_xor_sync(0xffffffffu, send, b);
        }
    }
    float l0 = P[0];     // lane l holds logit of neg l

    // ---- group B: negs 32..63 ----
    #pragma unroll
    for (int n = 0; n < 32; n++)
        P[n] = partial(__shfl_sync(0xffffffffu, i1, n));
    #pragma unroll
    for (int b = 16; b; b >>= 1) {
        #pragma unroll
        for (int j = 0; j < b; j++) {
            bool up = (lane & b) != 0;
            float keep = up ? P[j + b] : P[j];
            float send = up ? P[j] : P[j + b];
            P[j] = keep + __shfl_xor_sync(0xffffffffu, send, b);
        }
    }
    float l1 = P[0];

    // softmax over [m, l0(32), l1(32)]
    float mx = fmaxf(m, fmaxf(l0, l1));
    #pragma unroll
    for (int off = 16; off; off >>= 1)
        mx = fmaxf(mx, __shfl_xor_sync(0xffffffffu, mx, off));
    float se = __expf(l0 - mx) + __expf(l1 - mx);
    #pragma unroll
    for (int off = 16; off; off >>= 1)
        se += __shfl_xor_sync(0xffffffffu, se, off);
    float em = __expf(m - mx);
    se += em;
    float p0 = em / se;
    float loss = -__logf(p0 + EPSF);

    __shared__ float sacc[8];
    if (lane == 0) sacc[warp] = loss * (1.0f / (3.0f * rows));
    __syncthreads();
    if (threadIdx.x == 0) {
        float s = 0.f;
        #pragma unroll
        for (int i = 0; i < 8; i++) s += sacc[i];
        g_partial[bx] = s;
    }
}

// Deterministic final reduction
__global__ void finalize_kernel(int n, float* __restrict__ out)
{
    __shared__ float s[256];
    float acc = 0.f;
    for (int i = threadIdx.x; i < n; i += 256) acc += g_partial[i];
    s[threadIdx.x] = acc;
    __syncthreads();
    for (int st = 128; st; st >>= 1) {
        if (threadIdx.x < st) s[threadIdx.x] += s[threadIdx.x + st];
        __syncthreads();
    }
    if (threadIdx.x == 0) out[0] = s[0];
}

// ---------------------------------------------------------------------------
extern "C" void kernel_launch(void* const* d_in, const int* in_sizes, int n_in,
                              void* d_out, int out_size)
{
    const float* z   = (const float*)d_in[0];
    const float* cin = (const float*)d_in[1];
    const float* Wk  = (const float*)d_in[2];
    float* out = (float*)d_out;

    transpose_kernel<<<2 * Bdim * Wdim, 256>>>(z, cin);
    gemm_tf32_kernel<<<dim3(MB0 + MB1 + MB2, Cdim / 64), 256>>>(Wk);
    dot_kernel<<<DB0 + DB1 + DB2, 256>>>((const int*)d_in[3], (const int*)d_in[4],
                                         (const int*)d_in[5]);
    finalize_kernel<<<1, 256>>>(DB0 + DB1 + DB2, out);
}